// round 1
// baseline (speedup 1.0000x reference)
#include <cuda_runtime.h>
#include <cstdint>

// One thread = one image. All activations are +/-1, represented as bits
// (bit=1 <=> +1). Convs become XNOR+popcount; NAND threshold is a compare.
//
// Layer geometry (VALID, NCHW):
//  L0: 1x28x28  -> (16,2,2,s2) -> 16x14x14
//  L1: 16x14x14 -> (16,2,2,s2) -> 16x7x7
//  L2: 16x7x7   -> (16,2,2,s1) -> 16x6x6
//  L3: 16x6x6   -> (16,2,2,s2) -> 16x3x3
//  L4: 16x3x3   -> (16,2,2,s2) -> 16x1x1
//  L5: 16x1x1   -> (10,1,1,s1) -> 10x1x1
//
// y = sum(a*w) over T taps with a,w in {+/-1}; D = #mismatches; y = T - 2D.
// NAND output: +1 (bit 1) iff y <= 0 iff D >= T/2 (T even; y==0 -> +1).
//  L0: T=4  -> bit = (D >= 2)
//  L1-4: T=64 -> bit = (D >= 32)
//  L5: T=16 -> value = (D >= 8) ? +1 : -1

#define IMGS_PER_BLOCK 64
#define NTHREADS 64
#define NWORDS (IMGS_PER_BLOCK * 784 / 32)   // 1568

__global__ void __launch_bounds__(NTHREADS)
bnn_mnist_kernel(const float* __restrict__ x,
                 const float* __restrict__ w0, const float* __restrict__ w1,
                 const float* __restrict__ w2, const float* __restrict__ w3,
                 const float* __restrict__ w4, const float* __restrict__ w5,
                 float* __restrict__ out, int B)
{
    __shared__ uint32_t sbits[NWORDS + 1];   // packed input bits for this block
    __shared__ uint64_t sw[4][16];           // w1..w4 as 64-bit tap/channel masks
    __shared__ uint32_t sw0b[16];            // w0 4-bit masks per out channel
    __shared__ uint16_t sT0[16];             // L0 LUT: 4-bit patch -> 16-ch vector
    __shared__ uint16_t sw5[10];             // w5 16-bit masks

    const int tid = threadIdx.x;
    const int b0 = blockIdx.x * IMGS_PER_BLOCK;

    // ---------------- weight prep (tiny, redundant per block) ----------------
    {
        // w1..w4: 4 layers x 16 oc = 64 threads. Layout OIHW [16,16,2,2].
        // a64 / w64 bit layout: bit (tap*16 + ic), tap = kh*2+kw.
        int L = tid >> 4, oc = tid & 15;
        const float* wp = (L == 0 ? w1 : L == 1 ? w2 : L == 2 ? w3 : w4) + oc * 64;
        uint64_t v = 0;
#pragma unroll
        for (int ic = 0; ic < 16; ic++)
#pragma unroll
            for (int tap = 0; tap < 4; tap++)
                if (wp[ic * 4 + tap] > 0.0f) v |= 1ull << (tap * 16 + ic);
        sw[L][oc] = v;
    }
    if (tid < 16) {
        // w0: [16,1,2,2]; bit k = tap (kh,kw) with k = kh*2+kw
        uint32_t v = 0;
#pragma unroll
        for (int k = 0; k < 4; k++)
            if (w0[tid * 4 + k] > 0.0f) v |= 1u << k;
        sw0b[tid] = v;
    }
    if (tid < 10) {
        // w5: [10,16,1,1]
        uint32_t v = 0;
#pragma unroll
        for (int ic = 0; ic < 16; ic++)
            if (w5[tid * 16 + ic] > 0.0f) v |= 1u << ic;
        sw5[tid] = (uint16_t)v;
    }
    __syncthreads();
    if (tid < 16) {
        // L0 LUT: for each 4-bit input patch a, 16-bit output channel vector
        uint32_t acc = 0;
#pragma unroll
        for (int c = 0; c < 16; c++) {
            int D = __popc((uint32_t)(tid ^ sw0b[c]) & 0xFu);
            acc |= (uint32_t)(D >= 2) << c;
        }
        sT0[tid] = (uint16_t)acc;
    }
    if (tid == 0) sbits[NWORDS] = 0;   // pad word for funnel shifts

    // ---------------- coalesced load + binarize (ballot pack) ----------------
    {
        const int lane = tid & 31;
        const int warp = tid >> 5;
        const float* chunk = x + (size_t)b0 * 784;
        const int nfloats = (min(IMGS_PER_BLOCK, B - b0)) * 784;
        for (int w = warp; w < NWORDS; w += (NTHREADS / 32)) {
            int f = w * 32 + lane;
            float v = (f < nfloats) ? chunk[f] : 0.0f;
            unsigned b = __ballot_sync(0xFFFFFFFFu, v > 0.0f);
            if (lane == 0) sbits[w] = b;
        }
    }
    __syncthreads();

    const int img = b0 + tid;
    if (img >= B) return;

    const int bitbase = tid * 784;

    // ---------------- L0: 28x28 -> 16ch x 14x14 via LUT ----------------
    uint16_t act0[196];
#pragma unroll 1
    for (int i = 0; i < 14; i++) {
        int bpT = bitbase + 28 * (2 * i);
        int bpB = bpT + 28;
        uint32_t rT = __funnelshift_r(sbits[bpT >> 5], sbits[(bpT >> 5) + 1], bpT & 31) & 0x0FFFFFFFu;
        uint32_t rB = __funnelshift_r(sbits[bpB >> 5], sbits[(bpB >> 5) + 1], bpB & 31) & 0x0FFFFFFFu;
#pragma unroll
        for (int j = 0; j < 14; j++) {
            uint32_t a = ((rT >> (2 * j)) & 3u) | (((rB >> (2 * j)) & 3u) << 2);
            act0[i * 14 + j] = sT0[a];
        }
    }

    // ---------------- L1: 16x14x14 -> 16x7x7 (64-tap XNOR popcount) ----------------
    uint16_t act1[49];
#pragma unroll 1
    for (int i = 0; i < 7; i++) {
#pragma unroll 1
        for (int j = 0; j < 7; j++) {
            int p = (2 * i) * 14 + 2 * j;
            uint64_t a = (uint64_t)act0[p] | ((uint64_t)act0[p + 1] << 16)
                       | ((uint64_t)act0[p + 14] << 32) | ((uint64_t)act0[p + 15] << 48);
            uint32_t acc = 0;
#pragma unroll
            for (int oc = 0; oc < 16; oc++) {
                int D = __popcll(a ^ sw[0][oc]);
                acc |= (uint32_t)(D >= 32) << oc;
            }
            act1[i * 7 + j] = (uint16_t)acc;
        }
    }

    // ---------------- L2: 16x7x7 -> 16x6x6 (stride 1) ----------------
    uint16_t act2[36];
#pragma unroll 1
    for (int i = 0; i < 6; i++) {
#pragma unroll 1
        for (int j = 0; j < 6; j++) {
            int p = i * 7 + j;
            uint64_t a = (uint64_t)act1[p] | ((uint64_t)act1[p + 1] << 16)
                       | ((uint64_t)act1[p + 7] << 32) | ((uint64_t)act1[p + 8] << 48);
            uint32_t acc = 0;
#pragma unroll
            for (int oc = 0; oc < 16; oc++) {
                int D = __popcll(a ^ sw[1][oc]);
                acc |= (uint32_t)(D >= 32) << oc;
            }
            act2[i * 6 + j] = (uint16_t)acc;
        }
    }

    // ---------------- L3: 16x6x6 -> 16x3x3 (stride 2) ----------------
    uint16_t act3[9];
#pragma unroll 1
    for (int i = 0; i < 3; i++) {
#pragma unroll 1
        for (int j = 0; j < 3; j++) {
            int p = (2 * i) * 6 + 2 * j;
            uint64_t a = (uint64_t)act2[p] | ((uint64_t)act2[p + 1] << 16)
                       | ((uint64_t)act2[p + 6] << 32) | ((uint64_t)act2[p + 7] << 48);
            uint32_t acc = 0;
#pragma unroll
            for (int oc = 0; oc < 16; oc++) {
                int D = __popcll(a ^ sw[2][oc]);
                acc |= (uint32_t)(D >= 32) << oc;
            }
            act3[i * 3 + j] = (uint16_t)acc;
        }
    }

    // ---------------- L4: 16x3x3 -> 16x1x1 (stride 2, top-left 2x2) ----------------
    uint32_t act4;
    {
        uint64_t a = (uint64_t)act3[0] | ((uint64_t)act3[1] << 16)
                   | ((uint64_t)act3[3] << 32) | ((uint64_t)act3[4] << 48);
        uint32_t acc = 0;
#pragma unroll
        for (int oc = 0; oc < 16; oc++) {
            int D = __popcll(a ^ sw[3][oc]);
            acc |= (uint32_t)(D >= 32) << oc;
        }
        act4 = acc;
    }

    // ---------------- L5: 16 -> 10 classes, write +/-1.0f ----------------
    float* o = out + (size_t)img * 10;
#pragma unroll
    for (int oc = 0; oc < 10; oc++) {
        int D = __popc((act4 ^ (uint32_t)sw5[oc]) & 0xFFFFu);
        o[oc] = (D >= 8) ? 1.0f : -1.0f;
    }
}

extern "C" void kernel_launch(void* const* d_in, const int* in_sizes, int n_in,
                              void* d_out, int out_size)
{
    const float* x  = (const float*)d_in[0];
    const float* w0 = (const float*)d_in[1];
    const float* w1 = (const float*)d_in[2];
    const float* w2 = (const float*)d_in[3];
    const float* w3 = (const float*)d_in[4];
    const float* w4 = (const float*)d_in[5];
    const float* w5 = (const float*)d_in[6];
    float* out = (float*)d_out;

    int B = in_sizes[0] / 784;
    int grid = (B + IMGS_PER_BLOCK - 1) / IMGS_PER_BLOCK;
    bnn_mnist_kernel<<<grid, NTHREADS>>>(x, w0, w1, w2, w3, w4, w5, out, B);
}

// round 2
// speedup vs baseline: 1.0974x; 1.0974x over previous
#include <cuda_runtime.h>
#include <cstdint>

// Binarized NAND-conv net, one thread = one image, fully register-resident.
// bit=1 <=> +1. D = #mismatches over T taps; NAND out bit = (D >= T/2).
//  L0: 1x28x28 ->16x14x14 (T=4, via shfl LUT)   L1: ->16x7x7 (T=64)
//  L2: ->16x6x6  L3: ->16x3x3  L4: ->16x1x1 (all T=64)   L5: ->10 (T=16)

#define IMGS_PER_BLOCK 128
#define NTHREADS 128
#define NWORDS (IMGS_PER_BLOCK * 784 / 32)   // 3136

// 16-output-channel XNOR-popcount NAND step, T=64. W must be a register array.
__device__ __forceinline__ uint32_t nand16(uint64_t a, const uint64_t* W) {
    uint32_t acc = 0;
#pragma unroll
    for (int oc = 0; oc < 16; oc++) {
        uint64_t x = a ^ W[oc];
        uint32_t D = __popc((uint32_t)x) + __popc((uint32_t)(x >> 32)) + 32;
        acc |= (D >> 6) << oc;   // (D-32>=0) ? 1 : 0, D in [32,96]
    }
    return acc;
}

__global__ void __launch_bounds__(NTHREADS)
bnn_mnist_kernel(const float* __restrict__ x,
                 const float* __restrict__ w0, const float* __restrict__ w1,
                 const float* __restrict__ w2, const float* __restrict__ w3,
                 const float* __restrict__ w4, const float* __restrict__ w5,
                 float* __restrict__ out, int B)
{
    __shared__ uint32_t sbits[NWORDS + 1];
    __shared__ uint64_t sw_sh[4][16];
    __shared__ uint32_t sw0b[16];
    __shared__ uint32_t sw5s[10];

    const int tid = threadIdx.x;
    const int b0 = blockIdx.x * IMGS_PER_BLOCK;

    // ---- weight prep ----
    if (tid < 64) {
        int L = tid >> 4, oc = tid & 15;
        const float* wp = (L == 0 ? w1 : L == 1 ? w2 : L == 2 ? w3 : w4) + oc * 64;
        uint64_t v = 0;
#pragma unroll
        for (int ic = 0; ic < 16; ic++)
#pragma unroll
            for (int tap = 0; tap < 4; tap++)
                if (wp[ic * 4 + tap] > 0.0f) v |= 1ull << (tap * 16 + ic);
        sw_sh[L][oc] = v;
    } else if (tid < 80) {
        int c = tid - 64;
        uint32_t v = 0;
#pragma unroll
        for (int k = 0; k < 4; k++)
            if (w0[c * 4 + k] > 0.0f) v |= 1u << k;
        sw0b[c] = v;
    } else if (tid < 90) {
        int c = tid - 80;
        uint32_t v = 0;
#pragma unroll
        for (int ic = 0; ic < 16; ic++)
            if (w5[c * 16 + ic] > 0.0f) v |= 1u << ic;
        sw5s[c] = v;
    }
    if (tid == 0) sbits[NWORDS] = 0;

    // ---- coalesced load + binarize ----
    {
        const int lane = tid & 31;
        const int warp = tid >> 5;
        const float* chunk = x + (size_t)b0 * 784;
        const int nfloats = min(IMGS_PER_BLOCK, max(B - b0, 0)) * 784;
        for (int w = warp; w < NWORDS; w += (NTHREADS / 32)) {
            int f = w * 32 + lane;
            float v = (f < nfloats) ? chunk[f] : 0.0f;
            unsigned b = __ballot_sync(0xFFFFFFFFu, v > 0.0f);
            if (lane == 0) sbits[w] = b;
        }
    }
    __syncthreads();

    const int img = b0 + tid;
    const int bitbase = tid * 784;

    // ---- per-lane L0 LUT value: lane holds sT0[lane&15] ----
    uint32_t lutv;
    {
        const int patch = tid & 15;
        uint32_t a = 0;
#pragma unroll
        for (int c = 0; c < 16; c++)
            a |= (uint32_t)(__popc((patch ^ sw0b[c]) & 0xFu) >= 2) << c;
        lutv = a;
    }

    // ---- L0 fused into L1: stream 2 act0 rows at a time ----
    uint64_t W[16];
#pragma unroll
    for (int k = 0; k < 16; k++) W[k] = sw_sh[0][k];

    uint32_t act1[49];
#pragma unroll
    for (int i = 0; i < 7; i++) {
        uint32_t r[2][14];
#pragma unroll
        for (int rr = 0; rr < 2; rr++) {
            const int bpT = bitbase + 28 * (4 * i + 2 * rr);
            const int bpB = bpT + 28;
            uint32_t rT = __funnelshift_r(sbits[bpT >> 5], sbits[(bpT >> 5) + 1], bpT & 31) & 0x0FFFFFFFu;
            uint32_t rB = __funnelshift_r(sbits[bpB >> 5], sbits[(bpB >> 5) + 1], bpB & 31) & 0x0FFFFFFFu;
#pragma unroll
            for (int j = 0; j < 14; j++) {
                uint32_t a = ((rT >> (2 * j)) & 3u) | (((rB >> (2 * j)) & 3u) << 2);
                r[rr][j] = (uint32_t)__shfl_sync(0xFFFFFFFFu, lutv, (int)a) & 0xFFFFu;
            }
        }
#pragma unroll
        for (int j = 0; j < 7; j++) {
            uint64_t a64 = (uint64_t)r[0][2 * j] | ((uint64_t)r[0][2 * j + 1] << 16)
                         | ((uint64_t)r[1][2 * j] << 32) | ((uint64_t)r[1][2 * j + 1] << 48);
            act1[i * 7 + j] = nand16(a64, W);
        }
    }

    // ---- L2: 7x7 -> 6x6, stride 1 ----
#pragma unroll
    for (int k = 0; k < 16; k++) W[k] = sw_sh[1][k];
    uint32_t act2[36];
#pragma unroll
    for (int i = 0; i < 6; i++)
#pragma unroll
        for (int j = 0; j < 6; j++) {
            const int p = i * 7 + j;
            uint64_t a64 = (uint64_t)act1[p] | ((uint64_t)act1[p + 1] << 16)
                         | ((uint64_t)act1[p + 7] << 32) | ((uint64_t)act1[p + 8] << 48);
            act2[i * 6 + j] = nand16(a64, W);
        }

    // ---- L3: 6x6 -> 3x3, stride 2 ----
#pragma unroll
    for (int k = 0; k < 16; k++) W[k] = sw_sh[2][k];
    uint32_t act3[9];
#pragma unroll
    for (int i = 0; i < 3; i++)
#pragma unroll
        for (int j = 0; j < 3; j++) {
            const int p = (2 * i) * 6 + 2 * j;
            uint64_t a64 = (uint64_t)act2[p] | ((uint64_t)act2[p + 1] << 16)
                         | ((uint64_t)act2[p + 6] << 32) | ((uint64_t)act2[p + 7] << 48);
            act3[i * 3 + j] = nand16(a64, W);
        }

    // ---- L4: 3x3 -> 1x1, stride 2 ----
#pragma unroll
    for (int k = 0; k < 16; k++) W[k] = sw_sh[3][k];
    uint32_t act4;
    {
        uint64_t a64 = (uint64_t)act3[0] | ((uint64_t)act3[1] << 16)
                     | ((uint64_t)act3[3] << 32) | ((uint64_t)act3[4] << 48);
        act4 = nand16(a64, W);
    }

    // ---- L5: 16 -> 10 classes ----
    if (img < B) {
        float* o = out + (size_t)img * 10;
#pragma unroll
        for (int oc = 0; oc < 10; oc++) {
            uint32_t D = __popc((act4 ^ sw5s[oc]) & 0xFFFFu);
            o[oc] = (D >= 8) ? 1.0f : -1.0f;
        }
    }
}

extern "C" void kernel_launch(void* const* d_in, const int* in_sizes, int n_in,
                              void* d_out, int out_size)
{
    const float* x  = (const float*)d_in[0];
    const float* w0 = (const float*)d_in[1];
    const float* w1 = (const float*)d_in[2];
    const float* w2 = (const float*)d_in[3];
    const float* w3 = (const float*)d_in[4];
    const float* w4 = (const float*)d_in[5];
    const float* w5 = (const float*)d_in[6];
    float* out = (float*)d_out;

    int B = in_sizes[0] / 784;
    int grid = (B + IMGS_PER_BLOCK - 1) / IMGS_PER_BLOCK;
    bnn_mnist_kernel<<<grid, NTHREADS>>>(x, w0, w1, w2, w3, w4, w5, out, B);
}